// round 1
// baseline (speedup 1.0000x reference)
#include <cuda_runtime.h>
#include <math.h>

#define BB 32
#define SS 8192
#define DD 256
#define HH 256

// scratch (device globals: allocation-free rule)
__device__ float g_inp[BB * HH];     // x @ W_in^T + b_in
__device__ float g_Wt[DD * HH];      // W_ctx transposed -> [d][h]
__device__ float g_att[BB * SS];     // attention logits (pre-softmax, post 10*tanh)

// ---------------------------------------------------------------------------
// Kernel 1: inp[b,h] = b_in[h] + sum_d x[b,d] * W_in[h,d]
// ---------------------------------------------------------------------------
__global__ void k_inp(const float* __restrict__ x,
                      const float* __restrict__ W_in,
                      const float* __restrict__ b_in) {
    int b = blockIdx.x, h = threadIdx.x;
    __shared__ float xs[HH];
    xs[h] = x[b * HH + h];
    __syncthreads();
    float acc = b_in[h];
    const float* w = W_in + h * HH;
#pragma unroll 8
    for (int d0 = 0; d0 < HH; d0 += 4) {
        float4 w4 = *(const float4*)(w + d0);
        acc += xs[d0] * w4.x + xs[d0 + 1] * w4.y + xs[d0 + 2] * w4.z + xs[d0 + 3] * w4.w;
    }
    g_inp[b * HH + h] = acc;
}

// ---------------------------------------------------------------------------
// Kernel 2: Wt[d][h] = W_ctx[h][d]   (one-time transpose so main GEMM loads
// B-tiles coalesced)
// ---------------------------------------------------------------------------
__global__ void k_transpose(const float* __restrict__ W) {
    __shared__ float t[32][33];
    int h0 = blockIdx.x * 32, d0 = blockIdx.y * 32;
    t[threadIdx.y][threadIdx.x] = W[(h0 + threadIdx.y) * DD + d0 + threadIdx.x];
    __syncthreads();
    g_Wt[(d0 + threadIdx.y) * HH + h0 + threadIdx.x] = t[threadIdx.x][threadIdx.y];
}

// ---------------------------------------------------------------------------
// Kernel 3: fused GEMM + tanh-dot epilogue.
// Block = 64 seq positions x all 256 h, K=256 in tiles of 32.
// Thread (tm = warp 0..7, tn = lane 0..31) owns m = tm+8i, n = tn+32j.
// Epilogue: att[b,s] = 10*tanh( sum_h V[h]*tanh(inp[b,h]+b_ctx[h]+C[s,h]) )
// ---------------------------------------------------------------------------
#define TM 64
#define KT 32
__global__ __launch_bounds__(256) void k_main(const float* __restrict__ context,
                                              const float* __restrict__ b_ctx,
                                              const float* __restrict__ V) {
    __shared__ float As[TM][KT];       // 8 KB, [m][k]: warp-broadcast reads
    __shared__ float Bs[KT][HH];       // 32 KB, [k][n]: lane-stride-1 reads

    int b  = blockIdx.y;
    int m0 = blockIdx.x * TM;
    int tid = threadIdx.x;
    int tn = tid & 31;   // lane  -> n = tn + 32*j
    int tm = tid >> 5;   // warp  -> m = tm + 8*i

    float vv[8], ib[8];
#pragma unroll
    for (int j = 0; j < 8; j++) {
        int n = tn + 32 * j;
        vv[j] = V[n];
        ib[j] = g_inp[b * HH + n] + b_ctx[n];
    }

    float acc[8][8];
#pragma unroll
    for (int i = 0; i < 8; i++)
#pragma unroll
        for (int j = 0; j < 8; j++) acc[i][j] = 0.f;

    const float* ctx = context + ((long)b * SS + m0) * DD;

    for (int k0 = 0; k0 < DD; k0 += KT) {
        // A tile: 64x32 floats, 8 per thread (2x float4), direct [m][k] layout
        {
            int idx = tid * 8;
            int row = idx >> 5;
            int col = idx & 31;
            float4 a0 = *(const float4*)(ctx + row * DD + k0 + col);
            float4 a1 = *(const float4*)(ctx + row * DD + k0 + col + 4);
            *(float4*)(&As[row][col])     = a0;
            *(float4*)(&As[row][col + 4]) = a1;
        }
        // B tile: 32x256 floats from pre-transposed Wt, coalesced float4
#pragma unroll
        for (int r = 0; r < 8; r++) {
            int f  = tid + 256 * r;
            int k  = f >> 6;
            int n4 = f & 63;
            float4 v4 = *(const float4*)(g_Wt + (k0 + k) * HH + n4 * 4);
            *(float4*)(&Bs[k][n4 * 4]) = v4;
        }
        __syncthreads();

#pragma unroll
        for (int k = 0; k < KT; k++) {
            float a[8], bbv[8];
#pragma unroll
            for (int i = 0; i < 8; i++) a[i] = As[tm + 8 * i][k];   // broadcast
#pragma unroll
            for (int j = 0; j < 8; j++) bbv[j] = Bs[k][tn + 32 * j]; // stride-1
#pragma unroll
            for (int i = 0; i < 8; i++)
#pragma unroll
                for (int j = 0; j < 8; j++) acc[i][j] += a[i] * bbv[j];
        }
        __syncthreads();
    }

    // epilogue: per-row tanh-dot with V, warp reduction (warp == fixed tm)
#pragma unroll
    for (int i = 0; i < 8; i++) {
        float part = 0.f;
#pragma unroll
        for (int j = 0; j < 8; j++)
            part += vv[j] * tanhf(acc[i][j] + ib[j]);
#pragma unroll
        for (int off = 16; off; off >>= 1)
            part += __shfl_xor_sync(0xffffffffu, part, off);
        if (tn == 0)
            g_att[b * SS + m0 + tm + 8 * i] = 10.f * tanhf(part);
    }
}

// ---------------------------------------------------------------------------
// Kernel 4: per-batch masked argmax + p = 1/sum(exp(att - max)); echo mask.
// out layout: [indices(32) | p(32) | mask(32*8192)] as float32.
// ---------------------------------------------------------------------------
__global__ void k_reduce(const int* __restrict__ mask, float* __restrict__ out) {
    int b = blockIdx.x;
    int tid = threadIdx.x;
    __shared__ float smax[256];
    __shared__ int   sidx[256];

    float best = -INFINITY;
    int bidx = 0x7fffffff;
    for (int s = tid; s < SS; s += 256) {
        int m = mask[b * SS + s];
        out[2 * BB + b * SS + s] = m ? 1.f : 0.f;
        if (m) {
            float v = g_att[b * SS + s];
            if (v > best || (v == best && s < bidx)) { best = v; bidx = s; }
        }
    }
    smax[tid] = best; sidx[tid] = bidx;
    __syncthreads();
    for (int off = 128; off; off >>= 1) {
        if (tid < off) {
            float v = smax[tid + off]; int ix = sidx[tid + off];
            if (v > smax[tid] || (v == smax[tid] && ix < sidx[tid])) {
                smax[tid] = v; sidx[tid] = ix;
            }
        }
        __syncthreads();
    }
    float rowmax = smax[0];
    int rowidx = (rowmax == -INFINITY) ? 0 : sidx[0];
    __syncthreads();

    float se = 0.f;
    for (int s = tid; s < SS; s += 256) {
        if (mask[b * SS + s]) se += expf(g_att[b * SS + s] - rowmax);
    }
    smax[tid] = se;
    __syncthreads();
    for (int off = 128; off; off >>= 1) {
        if (tid < off) smax[tid] += smax[tid + off];
        __syncthreads();
    }
    if (tid == 0) {
        out[b]      = (float)rowidx;
        out[BB + b] = 1.f / smax[0];
    }
}

// ---------------------------------------------------------------------------
extern "C" void kernel_launch(void* const* d_in, const int* in_sizes, int n_in,
                              void* d_out, int out_size) {
    const float* x      = (const float*)d_in[0];  // [32,256]
    const float* contex = (const float*)d_in[1];  // [32,8192,256]
    const int*   mask   = (const int*)  d_in[2];  // [32,8192]
    const float* W_in   = (const float*)d_in[3];  // [256,256]
    const float* b_in   = (const float*)d_in[4];  // [256]
    const float* W_ctx  = (const float*)d_in[5];  // [256,256]
    const float* b_ctx  = (const float*)d_in[6];  // [256]
    const float* V      = (const float*)d_in[7];  // [256]
    float* out = (float*)d_out;

    k_inp<<<BB, HH>>>(x, W_in, b_in);
    k_transpose<<<dim3(HH / 32, DD / 32), dim3(32, 32)>>>(W_ctx);
    k_main<<<dim3(SS / TM, BB), 256>>>(contex, b_ctx, V);
    k_reduce<<<BB, 256>>>(mask, out);
}